// round 6
// baseline (speedup 1.0000x reference)
#include <cuda_runtime.h>

// RPE MHA, sm_100a. B=2, N=M=512, C=256, H=8, D=32.
// scores_p computed as embed . wq (wq = Wp-projected q), avoiding the
// (B*N*M,C)x(C,C) projection of embed.
// R5: fused kernel reworked to register-direct streaming of embed rows
// (no smem staging), static 24KB smem, 2-3 CTAs/SM.

#define SCALE_Q 0.17677669529663687f  // 32^-0.5, folded into q projection

__device__ float g_q[1024 * 256];
__device__ float g_k[1024 * 256];
__device__ float g_v[1024 * 256];
__device__ float g_wq[8 * 1024 * 256];     // [h][bn][c]
__device__ float g_se[16 * 512 * 512];     // [b*8+h][n][m]
__device__ float g_attn[16 * 512 * 512];   // [b*8+h][n][m]
__device__ float g_hid[1024 * 256];        // [bn][c]

// ---------------------------------------------------------------------------
// 64xN tiled fp32 GEMM, 256 threads, K-tile 16 (unchanged from R4 pass).
// ---------------------------------------------------------------------------
template <bool BT, int TN>
__device__ __forceinline__ void gemm_body(
    const float* __restrict__ A, int lda,
    const float* __restrict__ B, int ldb,
    float* __restrict__ C, int ldc,
    int N, int K, float scale, const float* __restrict__ bias)
{
    __shared__ float As[64][20];
    __shared__ float Bs[16][68];

    const int tid = threadIdx.x;
    const int m0 = blockIdx.x * 64;
    const int n0 = blockIdx.y * 64;
    const int lr = tid >> 2;
    const int lc = (tid & 3) << 2;

    constexpr int RM = (TN == 64) ? 4 : 2;
    const int ty = (TN == 64) ? (tid >> 4) : (tid >> 3);
    const int tx = (TN == 64) ? (tid & 15) : (tid & 7);

    float acc[RM][4];
#pragma unroll
    for (int i = 0; i < RM; i++)
#pragma unroll
        for (int j = 0; j < 4; j++) acc[i][j] = 0.0f;

    for (int k0 = 0; k0 < K; k0 += 16) {
        float4 a4 = *(const float4*)(A + (long)(m0 + lr) * lda + k0 + lc);
        *(float4*)&As[lr][lc] = a4;
        if (BT) {
            float4 b4 = *(const float4*)(B + (long)(n0 + lr) * ldb + k0 + lc);
            Bs[lc + 0][lr] = b4.x;
            Bs[lc + 1][lr] = b4.y;
            Bs[lc + 2][lr] = b4.z;
            Bs[lc + 3][lr] = b4.w;
        } else {
            const int bk = tid >> 4;
            const int bn = (tid & 15) << 2;
            float4 b4 = make_float4(0.f, 0.f, 0.f, 0.f);
            if (n0 + bn < N)
                b4 = *(const float4*)(B + (long)(k0 + bk) * ldb + n0 + bn);
            *(float4*)&Bs[bk][bn] = b4;
        }
        __syncthreads();

#pragma unroll
        for (int kk = 0; kk < 16; kk++) {
            float a[RM];
#pragma unroll
            for (int i = 0; i < RM; i++) a[i] = As[ty * RM + i][kk];
            float4 bb = *(const float4*)&Bs[kk][tx * 4];
#pragma unroll
            for (int i = 0; i < RM; i++) {
                acc[i][0] += a[i] * bb.x;
                acc[i][1] += a[i] * bb.y;
                acc[i][2] += a[i] * bb.z;
                acc[i][3] += a[i] * bb.w;
            }
        }
        __syncthreads();
    }

#pragma unroll
    for (int i = 0; i < RM; i++) {
#pragma unroll
        for (int j = 0; j < 4; j++) {
            int n = n0 + tx * 4 + j;
            if (n < N) {
                float v = acc[i][j] * scale;
                if (bias) v += bias[n];
                C[(long)(m0 + ty * RM + i) * ldc + n] = v;
            }
        }
    }
}

__device__ __forceinline__ long zoff(int z, long o1, long o2)
{
    return (long)(z >> 3) * o1 + (long)(z & 7) * o2;
}

__global__ void __launch_bounds__(256) k_gemm_nt(
    const float* A, int lda, long oA1, long oA2,
    const float* B, int ldb, long oB1, long oB2,
    float* C, int ldc, long oC1, long oC2,
    int N, int K, float scale)
{
    int z = blockIdx.z;
    gemm_body<true, 64>(A + zoff(z, oA1, oA2), lda,
                        B + zoff(z, oB1, oB2), ldb,
                        C + zoff(z, oC1, oC2), ldc, N, K, scale, nullptr);
}

__global__ void __launch_bounds__(256) k_gemm_nn64(
    const float* A, int lda, long oA1, long oA2,
    const float* B, int ldb, long oB1, long oB2,
    float* C, int ldc, long oC1, long oC2,
    int N, int K, float scale, const float* bias)
{
    int z = blockIdx.z;
    gemm_body<false, 64>(A + zoff(z, oA1, oA2), lda,
                         B + zoff(z, oB1, oB2), ldb,
                         C + zoff(z, oC1, oC2), ldc, N, K, scale, bias);
}

__global__ void __launch_bounds__(256) k_gemm_nn32(
    const float* A, int lda, long oA1, long oA2,
    const float* B, int ldb, long oB1, long oB2,
    float* C, int ldc, long oC1, long oC2,
    int N, int K, float scale)
{
    int z = blockIdx.z;
    gemm_body<false, 32>(A + zoff(z, oA1, oA2), lda,
                         B + zoff(z, oB1, oB2), ldb,
                         C + zoff(z, oC1, oC2), ldc, N, K, scale, nullptr);
}

__global__ void __launch_bounds__(256) k_gemm_qkv(
    const float* Aq, const float* Ak, const float* Av,
    const float* Bq, const float* Bk, const float* Bv,
    float* Cq, float* Ck, float* Cv)
{
    int z = blockIdx.z;
    const float* A = (z == 0) ? Aq : (z == 1) ? Ak : Av;
    const float* B = (z == 0) ? Bq : (z == 1) ? Bk : Bv;
    float*       C = (z == 0) ? Cq : (z == 1) ? Ck : Cv;
    gemm_body<false, 64>(A, 256, B, 256, C, 256, 256, 256,
                         (z == 0) ? SCALE_Q : 1.0f, nullptr);
}

// ---------------------------------------------------------------------------
// Fused scores_p + add scores_e + softmax -> attn.
// CTA per (b,n), 256 threads. Thread t streams embed rows m=t and m=t+256
// directly from gmem (LDG.128); wq broadcast from 8KB smem. No staging.
// Static smem 24KB -> multiple CTAs/SM.
// ---------------------------------------------------------------------------
__global__ void __launch_bounds__(256, 2) k_fused_score_softmax(
    const float* __restrict__ embed,  // [b][n][m][c]
    const float* __restrict__ wq,     // [h][bn][c]
    const float* __restrict__ se,     // [b*8+h][n][m]
    float* __restrict__ attn)         // [b*8+h][n][m]
{
    __shared__ float BsW[256 * 8];    // [c][h]
    __shared__ float S[8 * 512];      // [h][m]

    const int n = blockIdx.x;
    const int b = blockIdx.y;
    const int t = threadIdx.x;
    const long bn = (long)b * 512 + n;

    // wq -> BsW[c][h], c = t (one-time)
#pragma unroll
    for (int h = 0; h < 8; h++)
        BsW[t * 8 + h] = wq[((long)h * 1024 + bn) * 256 + t];
    __syncthreads();

    const float* E0 = embed + bn * 131072L + (long)t * 256;  // row m=t
    // row m=t+256 is E0 + 256*256

    float acc0[8], acc1[8];
#pragma unroll
    for (int h = 0; h < 8; h++) { acc0[h] = 0.f; acc1[h] = 0.f; }

    for (int ck = 0; ck < 16; ck++) {          // 16-channel chunks
        const float* e0 = E0 + ck * 16;
        float4 s0[4], s1[4];
#pragma unroll
        for (int j = 0; j < 4; j++) {
            s0[j] = *(const float4*)(e0 + j * 4);
            s1[j] = *(const float4*)(e0 + 65536 + j * 4);
        }
        const float* bw = BsW + ck * 128;      // 16 c * 8 h
#pragma unroll
        for (int j = 0; j < 4; j++) {
            float cv[4] = { s0[j].x, s0[j].y, s0[j].z, s0[j].w };
            float dv[4] = { s1[j].x, s1[j].y, s1[j].z, s1[j].w };
#pragma unroll
            for (int e = 0; e < 4; e++) {
                const float* w8 = bw + (j * 4 + e) * 8;
                float4 bA = *(const float4*)w8;        // heads 0..3 (uniform)
                float4 bB = *(const float4*)(w8 + 4);  // heads 4..7
                float a0 = cv[e], a1 = dv[e];
                acc0[0] += a0 * bA.x;  acc0[1] += a0 * bA.y;
                acc0[2] += a0 * bA.z;  acc0[3] += a0 * bA.w;
                acc0[4] += a0 * bB.x;  acc0[5] += a0 * bB.y;
                acc0[6] += a0 * bB.z;  acc0[7] += a0 * bB.w;
                acc1[0] += a1 * bA.x;  acc1[1] += a1 * bA.y;
                acc1[2] += a1 * bA.z;  acc1[3] += a1 * bA.w;
                acc1[4] += a1 * bB.x;  acc1[5] += a1 * bB.y;
                acc1[6] += a1 * bB.z;  acc1[7] += a1 * bB.w;
            }
        }
    }

    // add scores_e, stage to S[h][m]
    const float* seb = se + (long)(b * 8) * 262144 + (long)n * 512;
#pragma unroll
    for (int h = 0; h < 8; h++) {
        S[h * 512 + t]       = acc0[h] + seb[(long)h * 262144 + t];
        S[h * 512 + t + 256] = acc1[h] + seb[(long)h * 262144 + t + 256];
    }
    __syncthreads();

    // softmax: warp w -> head w, 512 values (16 per lane)
    const int w = t >> 5, l = t & 31;
    float* Sr = S + w * 512;
    float4 v[4];
    float mx = -3.0e38f;
#pragma unroll
    for (int k2 = 0; k2 < 4; k2++) {
        v[k2] = *(const float4*)(Sr + k2 * 128 + l * 4);
        mx = fmaxf(mx, fmaxf(fmaxf(v[k2].x, v[k2].y), fmaxf(v[k2].z, v[k2].w)));
    }
#pragma unroll
    for (int off = 16; off > 0; off >>= 1)
        mx = fmaxf(mx, __shfl_xor_sync(0xFFFFFFFFu, mx, off));

    float sum = 0.f;
#pragma unroll
    for (int k2 = 0; k2 < 4; k2++) {
        v[k2].x = __expf(v[k2].x - mx);
        v[k2].y = __expf(v[k2].y - mx);
        v[k2].z = __expf(v[k2].z - mx);
        v[k2].w = __expf(v[k2].w - mx);
        sum += v[k2].x + v[k2].y + v[k2].z + v[k2].w;
    }
#pragma unroll
    for (int off = 16; off > 0; off >>= 1)
        sum += __shfl_xor_sync(0xFFFFFFFFu, sum, off);

    const float inv = 1.0f / sum;
    float* ab = attn + (long)(b * 8 + w) * 262144 + (long)n * 512;
#pragma unroll
    for (int k2 = 0; k2 < 4; k2++) {
        v[k2].x *= inv; v[k2].y *= inv; v[k2].z *= inv; v[k2].w *= inv;
        *(float4*)(ab + k2 * 128 + l * 4) = v[k2];
    }
}

extern "C" void kernel_launch(void* const* d_in, const int* in_sizes, int n_in,
                              void* d_out, int out_size)
{
    const float* iq    = (const float*)d_in[0];
    const float* ik    = (const float*)d_in[1];
    const float* iv    = (const float*)d_in[2];
    const float* embed = (const float*)d_in[3];
    const float* Wq    = (const float*)d_in[4];
    const float* Wk    = (const float*)d_in[5];
    const float* Wv    = (const float*)d_in[6];
    const float* Wp    = (const float*)d_in[7];
    const float* Wout  = (const float*)d_in[8];
    const float* bout  = (const float*)d_in[9];
    float* out = (float*)d_out;

    float *q, *k, *v, *wq, *se, *attn, *hid;
    cudaGetSymbolAddress((void**)&q,    g_q);
    cudaGetSymbolAddress((void**)&k,    g_k);
    cudaGetSymbolAddress((void**)&v,    g_v);
    cudaGetSymbolAddress((void**)&wq,   g_wq);
    cudaGetSymbolAddress((void**)&se,   g_se);
    cudaGetSymbolAddress((void**)&attn, g_attn);
    cudaGetSymbolAddress((void**)&hid,  g_hid);

    // 1. q/k/v projections (q scaled)
    k_gemm_qkv<<<dim3(16, 4, 3), 256>>>(iq, ik, iv, Wq, Wk, Wv, q, k, v);

    // 2. wq[h] = Q_h @ Wp_h^T  (z = h, K = 32)
    k_gemm_nt<<<dim3(16, 4, 8), 256>>>(
        q, 256, 0, 32,
        Wp, 256, 0, 32,
        wq, 256, 0, 262144,
        256, 32, 1.0f);

    // 3. scores_e[b*8+h] = Q_h @ K_h^T  (z = b*8+h, K = 32)
    k_gemm_nt<<<dim3(8, 8, 16), 256>>>(
        q, 256, 131072, 32,
        k, 256, 131072, 32,
        se, 512, 2097152, 262144,
        512, 32, 1.0f);

    // 4. fused scores_p + softmax -> attn
    k_fused_score_softmax<<<dim3(512, 2), 256>>>(embed, wq, se, attn);

    // 5. hidden = attn @ V_h  (z = b*8+h, N = 32, K = 512)
    k_gemm_nn32<<<dim3(8, 1, 16), 256>>>(
        attn, 512, 2097152, 262144,
        v, 256, 131072, 32,
        hid, 256, 131072, 32,
        32, 512, 1.0f);

    // 6. out = hidden @ Wout + bout
    k_gemm_nn64<<<dim3(16, 4, 1), 256>>>(
        hid, 256, 0, 0,
        Wout, 256, 0, 0,
        out, 256, 0, 0,
        256, 256, 1.0f, bout);
}

// round 7
// speedup vs baseline: 1.1972x; 1.1972x over previous
#include <cuda_runtime.h>

// RPE MHA, sm_100a. B=2, N=M=512, C=256, H=8, D=32.
// scores_p = embed . wq with wq = Wp-projected q (avoids projecting embed).
// R6: fused kernel row-per-warp, warp-coalesced LDG, 9-shuffle head reduce.

#define SCALE_Q 0.17677669529663687f  // 32^-0.5, folded into q projection

__device__ float g_q[1024 * 256];
__device__ float g_k[1024 * 256];
__device__ float g_v[1024 * 256];
__device__ float g_wq[8 * 1024 * 256];     // [h][bn][c]
__device__ float g_se[16 * 512 * 512];     // [b*8+h][n][m]
__device__ float g_attn[16 * 512 * 512];   // [b*8+h][n][m]
__device__ float g_hid[1024 * 256];        // [bn][c]

// ---------------------------------------------------------------------------
// 64xN tiled fp32 GEMM, 256 threads, K-tile 16 (unchanged, known-good).
// ---------------------------------------------------------------------------
template <bool BT, int TN>
__device__ __forceinline__ void gemm_body(
    const float* __restrict__ A, int lda,
    const float* __restrict__ B, int ldb,
    float* __restrict__ C, int ldc,
    int N, int K, float scale, const float* __restrict__ bias)
{
    __shared__ float As[64][20];
    __shared__ float Bs[16][68];

    const int tid = threadIdx.x;
    const int m0 = blockIdx.x * 64;
    const int n0 = blockIdx.y * 64;
    const int lr = tid >> 2;
    const int lc = (tid & 3) << 2;

    constexpr int RM = (TN == 64) ? 4 : 2;
    const int ty = (TN == 64) ? (tid >> 4) : (tid >> 3);
    const int tx = (TN == 64) ? (tid & 15) : (tid & 7);

    float acc[RM][4];
#pragma unroll
    for (int i = 0; i < RM; i++)
#pragma unroll
        for (int j = 0; j < 4; j++) acc[i][j] = 0.0f;

    for (int k0 = 0; k0 < K; k0 += 16) {
        float4 a4 = *(const float4*)(A + (long)(m0 + lr) * lda + k0 + lc);
        *(float4*)&As[lr][lc] = a4;
        if (BT) {
            float4 b4 = *(const float4*)(B + (long)(n0 + lr) * ldb + k0 + lc);
            Bs[lc + 0][lr] = b4.x;
            Bs[lc + 1][lr] = b4.y;
            Bs[lc + 2][lr] = b4.z;
            Bs[lc + 3][lr] = b4.w;
        } else {
            const int bk = tid >> 4;
            const int bn = (tid & 15) << 2;
            float4 b4 = make_float4(0.f, 0.f, 0.f, 0.f);
            if (n0 + bn < N)
                b4 = *(const float4*)(B + (long)(k0 + bk) * ldb + n0 + bn);
            *(float4*)&Bs[bk][bn] = b4;
        }
        __syncthreads();

#pragma unroll
        for (int kk = 0; kk < 16; kk++) {
            float a[RM];
#pragma unroll
            for (int i = 0; i < RM; i++) a[i] = As[ty * RM + i][kk];
            float4 bb = *(const float4*)&Bs[kk][tx * 4];
#pragma unroll
            for (int i = 0; i < RM; i++) {
                acc[i][0] += a[i] * bb.x;
                acc[i][1] += a[i] * bb.y;
                acc[i][2] += a[i] * bb.z;
                acc[i][3] += a[i] * bb.w;
            }
        }
        __syncthreads();
    }

#pragma unroll
    for (int i = 0; i < RM; i++) {
#pragma unroll
        for (int j = 0; j < 4; j++) {
            int n = n0 + tx * 4 + j;
            if (n < N) {
                float v = acc[i][j] * scale;
                if (bias) v += bias[n];
                C[(long)(m0 + ty * RM + i) * ldc + n] = v;
            }
        }
    }
}

__device__ __forceinline__ long zoff(int z, long o1, long o2)
{
    return (long)(z >> 3) * o1 + (long)(z & 7) * o2;
}

__global__ void __launch_bounds__(256) k_gemm_nt(
    const float* A, int lda, long oA1, long oA2,
    const float* B, int ldb, long oB1, long oB2,
    float* C, int ldc, long oC1, long oC2,
    int N, int K, float scale)
{
    int z = blockIdx.z;
    gemm_body<true, 64>(A + zoff(z, oA1, oA2), lda,
                        B + zoff(z, oB1, oB2), ldb,
                        C + zoff(z, oC1, oC2), ldc, N, K, scale, nullptr);
}

__global__ void __launch_bounds__(256) k_gemm_nn64(
    const float* A, int lda, long oA1, long oA2,
    const float* B, int ldb, long oB1, long oB2,
    float* C, int ldc, long oC1, long oC2,
    int N, int K, float scale, const float* bias)
{
    int z = blockIdx.z;
    gemm_body<false, 64>(A + zoff(z, oA1, oA2), lda,
                         B + zoff(z, oB1, oB2), ldb,
                         C + zoff(z, oC1, oC2), ldc, N, K, scale, bias);
}

__global__ void __launch_bounds__(256) k_gemm_nn32(
    const float* A, int lda, long oA1, long oA2,
    const float* B, int ldb, long oB1, long oB2,
    float* C, int ldc, long oC1, long oC2,
    int N, int K, float scale)
{
    int z = blockIdx.z;
    gemm_body<false, 32>(A + zoff(z, oA1, oA2), lda,
                         B + zoff(z, oB1, oB2), ldb,
                         C + zoff(z, oC1, oC2), ldc, N, K, scale, nullptr);
}

__global__ void __launch_bounds__(256) k_gemm_qkv(
    const float* Aq, const float* Ak, const float* Av,
    const float* Bq, const float* Bk, const float* Bv,
    float* Cq, float* Ck, float* Cv)
{
    int z = blockIdx.z;
    const float* A = (z == 0) ? Aq : (z == 1) ? Ak : Av;
    const float* B = (z == 0) ? Bq : (z == 1) ? Bk : Bv;
    float*       C = (z == 0) ? Cq : (z == 1) ? Ck : Cv;
    gemm_body<false, 64>(A, 256, B, 256, C, 256, 256, 256,
                         (z == 0) ? SCALE_Q : 1.0f, nullptr);
}

// ---------------------------------------------------------------------------
// Fused scores_p + scores_e + softmax -> attn.
// CTA per (b,n), 256 threads. Warp w owns rows m in [64w, 64w+64).
// Per row: 2 coalesced LDG.128 (warp covers the whole 1KB row),
// lane computes 8 head-partials from its 8 channels (wq slice in 64 regs),
// then 8->4->2->1 head-interleaved butterfly + 2 full adds (9 shuffles).
// ---------------------------------------------------------------------------
__global__ void __launch_bounds__(256, 2) k_fused_score_softmax(
    const float* __restrict__ embed,  // [b][n][m][c]
    const float* __restrict__ wq,     // [h][bn][c]
    const float* __restrict__ se,     // [b*8+h][n][m]
    float* __restrict__ attn)         // [b*8+h][n][m]
{
    __shared__ float S[8 * 520];      // [h][m], pitch 520 (store conflicts)

    const int n = blockIdx.x;
    const int b = blockIdx.y;
    const int t = threadIdx.x;
    const int w = t >> 5, l = t & 31;
    const long bn = (long)b * 512 + n;

    // per-lane wq slice: channels 4l..4l+3 and 128+4l..128+4l+3, 8 heads
    float4 wq0[8], wq1[8];
#pragma unroll
    for (int h = 0; h < 8; h++) {
        const float* wp = wq + ((long)h * 1024 + bn) * 256;
        wq0[h] = *(const float4*)(wp + 4 * l);
        wq1[h] = *(const float4*)(wp + 128 + 4 * l);
    }

    // head owned by lane l after the 3 butterfly stages
    const int hid = ((l & 1) << 2) | (l & 2) | ((l & 4) >> 2);

    const float4* E = (const float4*)(embed + bn * 131072L) + (long)(w << 6) * 64;

#pragma unroll 2
    for (int i = 0; i < 64; i++) {
        const int m = (w << 6) + i;
        float4 x0 = E[i * 64 + l];        // c = 4l       (coalesced 512B)
        float4 x1 = E[i * 64 + 32 + l];   // c = 128 + 4l (coalesced 512B)

        float a[8];
#pragma unroll
        for (int h = 0; h < 8; h++) {
            a[h] = x0.x * wq0[h].x + x0.y * wq0[h].y
                 + x0.z * wq0[h].z + x0.w * wq0[h].w
                 + x1.x * wq1[h].x + x1.y * wq1[h].y
                 + x1.z * wq1[h].z + x1.w * wq1[h].w;
        }

        // 8 -> 4 (xor 1): even lane keeps heads 0-3, odd keeps 4-7
        float r[4];
#pragma unroll
        for (int j = 0; j < 4; j++) {
            float send = (l & 1) ? a[j] : a[j + 4];
            float keep = (l & 1) ? a[j + 4] : a[j];
            r[j] = keep + __shfl_xor_sync(0xFFFFFFFFu, send, 1);
        }
        // 4 -> 2 (xor 2)
        float r2[2];
#pragma unroll
        for (int j = 0; j < 2; j++) {
            float send = (l & 2) ? r[j] : r[j + 2];
            float keep = (l & 2) ? r[j + 2] : r[j];
            r2[j] = keep + __shfl_xor_sync(0xFFFFFFFFu, send, 2);
        }
        // 2 -> 1 (xor 4)
        float send = (l & 4) ? r2[0] : r2[1];
        float keep = (l & 4) ? r2[1] : r2[0];
        float s = keep + __shfl_xor_sync(0xFFFFFFFFu, send, 4);
        // full sums
        s += __shfl_xor_sync(0xFFFFFFFFu, s, 8);
        s += __shfl_xor_sync(0xFFFFFFFFu, s, 16);

        if (l < 8) S[hid * 520 + m] = s;
    }
    __syncthreads();

    // softmax: warp w -> head w; lane owns m = {64j + 2l, +1}, j = 0..7
    const float* Sr  = S + w * 520;
    const float* ser = se + (long)(b * 8 + w) * 262144 + (long)n * 512;
    float v[16];
    float mx = -3.0e38f;
#pragma unroll
    for (int j = 0; j < 8; j++) {
        float2 sv = *(const float2*)(Sr  + j * 64 + l * 2);
        float2 ev = *(const float2*)(ser + j * 64 + l * 2);
        v[2 * j]     = sv.x + ev.x;
        v[2 * j + 1] = sv.y + ev.y;
        mx = fmaxf(mx, fmaxf(v[2 * j], v[2 * j + 1]));
    }
#pragma unroll
    for (int off = 16; off > 0; off >>= 1)
        mx = fmaxf(mx, __shfl_xor_sync(0xFFFFFFFFu, mx, off));

    float sum = 0.f;
#pragma unroll
    for (int j = 0; j < 16; j++) {
        v[j] = __expf(v[j] - mx);
        sum += v[j];
    }
#pragma unroll
    for (int off = 16; off > 0; off >>= 1)
        sum += __shfl_xor_sync(0xFFFFFFFFu, sum, off);

    const float inv = 1.0f / sum;
    float* ab = attn + (long)(b * 8 + w) * 262144 + (long)n * 512;
#pragma unroll
    for (int j = 0; j < 8; j++)
        *(float2*)(ab + j * 64 + l * 2) =
            make_float2(v[2 * j] * inv, v[2 * j + 1] * inv);
}

extern "C" void kernel_launch(void* const* d_in, const int* in_sizes, int n_in,
                              void* d_out, int out_size)
{
    const float* iq    = (const float*)d_in[0];
    const float* ik    = (const float*)d_in[1];
    const float* iv    = (const float*)d_in[2];
    const float* embed = (const float*)d_in[3];
    const float* Wq    = (const float*)d_in[4];
    const float* Wk    = (const float*)d_in[5];
    const float* Wv    = (const float*)d_in[6];
    const float* Wp    = (const float*)d_in[7];
    const float* Wout  = (const float*)d_in[8];
    const float* bout  = (const float*)d_in[9];
    float* out = (float*)d_out;

    float *q, *k, *v, *wq, *se, *attn, *hid;
    cudaGetSymbolAddress((void**)&q,    g_q);
    cudaGetSymbolAddress((void**)&k,    g_k);
    cudaGetSymbolAddress((void**)&v,    g_v);
    cudaGetSymbolAddress((void**)&wq,   g_wq);
    cudaGetSymbolAddress((void**)&se,   g_se);
    cudaGetSymbolAddress((void**)&attn, g_attn);
    cudaGetSymbolAddress((void**)&hid,  g_hid);

    // 1. q/k/v projections (q scaled)
    k_gemm_qkv<<<dim3(16, 4, 3), 256>>>(iq, ik, iv, Wq, Wk, Wv, q, k, v);

    // 2. wq[h] = Q_h @ Wp_h^T  (z = h, K = 32)
    k_gemm_nt<<<dim3(16, 4, 8), 256>>>(
        q, 256, 0, 32,
        Wp, 256, 0, 32,
        wq, 256, 0, 262144,
        256, 32, 1.0f);

    // 3. scores_e[b*8+h] = Q_h @ K_h^T  (z = b*8+h, K = 32)
    k_gemm_nt<<<dim3(8, 8, 16), 256>>>(
        q, 256, 131072, 32,
        k, 256, 131072, 32,
        se, 512, 2097152, 262144,
        512, 32, 1.0f);

    // 4. fused scores_p + scores_e + softmax -> attn
    k_fused_score_softmax<<<dim3(512, 2), 256>>>(embed, wq, se, attn);

    // 5. hidden = attn @ V_h  (z = b*8+h, N = 32, K = 512)
    k_gemm_nn32<<<dim3(8, 1, 16), 256>>>(
        attn, 512, 2097152, 262144,
        v, 256, 131072, 32,
        hid, 256, 131072, 32,
        32, 512, 1.0f);

    // 6. out = hidden @ Wout + bout
    k_gemm_nn64<<<dim3(16, 4, 1), 256>>>(
        hid, 256, 0, 0,
        Wout, 256, 0, 0,
        out, 256, 0, 0,
        256, 256, 1.0f, bout);
}

// round 8
// speedup vs baseline: 1.4201x; 1.1861x over previous
#include <cuda_runtime.h>

// RPE MHA, sm_100a. B=2, N=M=512, C=256, H=8, D=32.
// scores_p = embed . wq with wq = Wp-projected q (avoids projecting embed).
// R7: attn@V fused into score/softmax kernel (V via L2), prefetch pipelining,
// merged wq+scores_e launch, double-buffered side GEMMs.

#define SCALE_Q 0.17677669529663687f  // 32^-0.5, folded into q projection

__device__ float g_q[1024 * 256];
__device__ float g_k[1024 * 256];
__device__ float g_v[1024 * 256];
__device__ float g_wq[8 * 1024 * 256];     // [h][bn][c]
__device__ float g_se[16 * 512 * 512];     // [b*8+h][n][m]
__device__ float g_hid[1024 * 256];        // [bn][c]

// ---------------------------------------------------------------------------
// 64x64 tiled fp32 GEMM, 256 threads, K-tile 16, register double-buffered.
// BT=false: C = A[m][k] @ B[k][n].  BT=true: C = A[m][k] @ B[n][k].
// ---------------------------------------------------------------------------
template <bool BT>
__device__ __forceinline__ void gemm_body(
    const float* __restrict__ A, int lda,
    const float* __restrict__ B, int ldb,
    float* __restrict__ C, int ldc,
    int N, int K, float scale, const float* __restrict__ bias)
{
    __shared__ float As[64][20];
    __shared__ float Bs[16][68];

    const int tid = threadIdx.x;
    const int m0 = blockIdx.x * 64;
    const int n0 = blockIdx.y * 64;
    const int lr = tid >> 2;
    const int lc = (tid & 3) << 2;
    const int bk = tid >> 4;
    const int bn_ = (tid & 15) << 2;
    const int ty = tid >> 4;
    const int tx = tid & 15;

    float acc[4][4];
#pragma unroll
    for (int i = 0; i < 4; i++)
#pragma unroll
        for (int j = 0; j < 4; j++) acc[i][j] = 0.0f;

    // prime first tile into registers
    float4 a4 = *(const float4*)(A + (long)(m0 + lr) * lda + lc);
    float4 b4;
    if (BT) {
        b4 = *(const float4*)(B + (long)(n0 + lr) * ldb + lc);
    } else {
        b4 = make_float4(0.f, 0.f, 0.f, 0.f);
        if (n0 + bn_ < N)
            b4 = *(const float4*)(B + (long)bk * ldb + n0 + bn_);
    }

    for (int k0 = 0; k0 < K; k0 += 16) {
        *(float4*)&As[lr][lc] = a4;
        if (BT) {
            Bs[lc + 0][lr] = b4.x;
            Bs[lc + 1][lr] = b4.y;
            Bs[lc + 2][lr] = b4.z;
            Bs[lc + 3][lr] = b4.w;
        } else {
            *(float4*)&Bs[bk][bn_] = b4;
        }
        __syncthreads();

        if (k0 + 16 < K) {   // prefetch next tile (overlaps with compute)
            a4 = *(const float4*)(A + (long)(m0 + lr) * lda + k0 + 16 + lc);
            if (BT) {
                b4 = *(const float4*)(B + (long)(n0 + lr) * ldb + k0 + 16 + lc);
            } else {
                b4 = make_float4(0.f, 0.f, 0.f, 0.f);
                if (n0 + bn_ < N)
                    b4 = *(const float4*)(B + (long)(k0 + 16 + bk) * ldb + n0 + bn_);
            }
        }

#pragma unroll
        for (int kk = 0; kk < 16; kk++) {
            float a[4];
#pragma unroll
            for (int i = 0; i < 4; i++) a[i] = As[ty * 4 + i][kk];
            float4 bb = *(const float4*)&Bs[kk][tx * 4];
#pragma unroll
            for (int i = 0; i < 4; i++) {
                acc[i][0] += a[i] * bb.x;
                acc[i][1] += a[i] * bb.y;
                acc[i][2] += a[i] * bb.z;
                acc[i][3] += a[i] * bb.w;
            }
        }
        __syncthreads();
    }

#pragma unroll
    for (int i = 0; i < 4; i++) {
#pragma unroll
        for (int j = 0; j < 4; j++) {
            int nn = n0 + tx * 4 + j;
            if (nn < N) {
                float val = acc[i][j] * scale;
                if (bias) val += bias[nn];
                C[(long)(m0 + ty * 4 + i) * ldc + nn] = val;
            }
        }
    }
}

// q/k/v projections batched over grid.z
__global__ void __launch_bounds__(256) k_gemm_qkv(
    const float* Aq, const float* Ak, const float* Av,
    const float* Bq, const float* Bk, const float* Bv,
    float* Cq, float* Ck, float* Cv)
{
    int z = blockIdx.z;
    const float* A = (z == 0) ? Aq : (z == 1) ? Ak : Av;
    const float* B = (z == 0) ? Bq : (z == 1) ? Bk : Bv;
    float*       C = (z == 0) ? Cq : (z == 1) ? Ck : Cv;
    gemm_body<false>(A, 256, B, 256, C, 256, 256, 256,
                     (z == 0) ? SCALE_Q : 1.0f, nullptr);
}

// Combined wq + scores_e (both depend only on q/k). grid (16, 8, 24).
//   z in [0,8):  wq[h] = Q_h @ Wp_h^T     (M=1024, N=256, K=32)
//   z in [8,24): se[b*8+h] = Q_h @ K_h^T  (M=512,  N=512, K=32)
__global__ void __launch_bounds__(256) k_wq_se(
    const float* __restrict__ q, const float* __restrict__ kmat,
    const float* __restrict__ Wp,
    float* __restrict__ wqo, float* __restrict__ seo)
{
    int z = blockIdx.z;
    if (z < 8) {
        if (blockIdx.y >= 4) return;
        gemm_body<true>(q + z * 32, 256,
                        Wp + z * 32, 256,
                        wqo + (long)z * 262144, 256,
                        256, 32, 1.0f, nullptr);
    } else {
        if (blockIdx.x >= 8) return;
        int zz = z - 8, bb = zz >> 3, hh = zz & 7;
        gemm_body<true>(q + (long)bb * 131072 + hh * 32, 256,
                        kmat + (long)bb * 131072 + hh * 32, 256,
                        seo + (long)zz * 262144, 512,
                        512, 32, 1.0f, nullptr);
    }
}

// out = hidden @ Wout + bout
__global__ void __launch_bounds__(256) k_gemm_out(
    const float* A, const float* B, float* C, const float* bias)
{
    gemm_body<false>(A, 256, B, 256, C, 256, 256, 256, 1.0f, bias);
}

// ---------------------------------------------------------------------------
// Fused scores_p + scores_e + softmax + attn@V -> hidden.
// CTA per (b,n), 256 threads. Warp w owns rows m in [64w, 64w+64) for the
// score phase and head w for softmax + PV.
// ---------------------------------------------------------------------------
__device__ __forceinline__ float reduce8(const float* a, int l)
{
    // 8 head-partials per lane -> per-head warp sums; lanes 0..7 end up
    // holding heads per the hlane mapping (bit-reversed 3-bit).
    float r[4];
#pragma unroll
    for (int j = 0; j < 4; j++) {
        float send = (l & 1) ? a[j] : a[j + 4];
        float keep = (l & 1) ? a[j + 4] : a[j];
        r[j] = keep + __shfl_xor_sync(0xFFFFFFFFu, send, 1);
    }
    float r2[2];
#pragma unroll
    for (int j = 0; j < 2; j++) {
        float send = (l & 2) ? r[j] : r[j + 2];
        float keep = (l & 2) ? r[j + 2] : r[j];
        r2[j] = keep + __shfl_xor_sync(0xFFFFFFFFu, send, 2);
    }
    float send = (l & 4) ? r2[0] : r2[1];
    float keep = (l & 4) ? r2[1] : r2[0];
    float s = keep + __shfl_xor_sync(0xFFFFFFFFu, send, 4);
    s += __shfl_xor_sync(0xFFFFFFFFu, s, 8);
    s += __shfl_xor_sync(0xFFFFFFFFu, s, 16);
    return s;
}

__global__ void __launch_bounds__(256, 2) k_fused(
    const float* __restrict__ embed,  // [b][n][m][c]
    const float* __restrict__ wq,     // [h][bn][c]
    const float* __restrict__ se,     // [b*8+h][n][m]
    const float* __restrict__ vmat,   // [b*512+m][c]
    float* __restrict__ hid)          // [bn][c]
{
    __shared__ float S[8 * 520];      // [h][m], pitch 520

    const int n = blockIdx.x;
    const int b = blockIdx.y;
    const int t = threadIdx.x;
    const int w = t >> 5, l = t & 31;
    const long bn = (long)b * 512 + n;

    // per-lane wq slice: channels 4l..4l+3 and 128+4l..128+4l+3, 8 heads
    float4 wq0[8], wq1[8];
#pragma unroll
    for (int h = 0; h < 8; h++) {
        const float* wp = wq + ((long)h * 1024 + bn) * 256;
        wq0[h] = *(const float4*)(wp + 4 * l);
        wq1[h] = *(const float4*)(wp + 128 + 4 * l);
    }
    const int hlane = ((l & 1) << 2) | (l & 2) | ((l & 4) >> 2);

    const float4* E = (const float4*)(embed + bn * 131072L) + (long)(w << 6) * 64;

    // prime prefetch: rows 0, 1 of this warp's 64-row block
    float4 p0 = E[l], p1 = E[32 + l], p2 = E[64 + l], p3 = E[96 + l];

    for (int i = 0; i < 64; i += 2) {
        float4 x0 = p0, x1 = p1, y0 = p2, y1 = p3;
        if (i + 2 < 64) {
            const float4* En = E + (i + 2) * 64;
            p0 = En[l]; p1 = En[32 + l]; p2 = En[64 + l]; p3 = En[96 + l];
        }

        float a[8], c[8];
#pragma unroll
        for (int h = 0; h < 8; h++) {
            a[h] = x0.x * wq0[h].x + x0.y * wq0[h].y
                 + x0.z * wq0[h].z + x0.w * wq0[h].w
                 + x1.x * wq1[h].x + x1.y * wq1[h].y
                 + x1.z * wq1[h].z + x1.w * wq1[h].w;
            c[h] = y0.x * wq0[h].x + y0.y * wq0[h].y
                 + y0.z * wq0[h].z + y0.w * wq0[h].w
                 + y1.x * wq1[h].x + y1.y * wq1[h].y
                 + y1.z * wq1[h].z + y1.w * wq1[h].w;
        }
        float sA = reduce8(a, l);
        float sB = reduce8(c, l);
        if (l < 8) {
            S[hlane * 520 + (w << 6) + i]     = sA;
            S[hlane * 520 + (w << 6) + i + 1] = sB;
        }
    }
    __syncthreads();

    // softmax: warp w -> head w; lane owns m = {64j + 2l, +1}, j = 0..7
    const float* Sr  = S + w * 520;
    const float* ser = se + (long)(b * 8 + w) * 262144 + (long)n * 512;
    float v[16];
    float mx = -3.0e38f;
#pragma unroll
    for (int j = 0; j < 8; j++) {
        float2 sv = *(const float2*)(Sr  + j * 64 + l * 2);
        float2 ev = *(const float2*)(ser + j * 64 + l * 2);
        v[2 * j]     = sv.x + ev.x;
        v[2 * j + 1] = sv.y + ev.y;
        mx = fmaxf(mx, fmaxf(v[2 * j], v[2 * j + 1]));
    }
#pragma unroll
    for (int off = 16; off > 0; off >>= 1)
        mx = fmaxf(mx, __shfl_xor_sync(0xFFFFFFFFu, mx, off));

    float sum = 0.f;
#pragma unroll
    for (int j = 0; j < 16; j++) {
        v[j] = __expf(v[j] - mx);
        sum += v[j];
    }
#pragma unroll
    for (int off = 16; off > 0; off >>= 1)
        sum += __shfl_xor_sync(0xFFFFFFFFu, sum, off);

    const float inv = 1.0f / sum;
#pragma unroll
    for (int j = 0; j < 16; j++) v[j] *= inv;

    // PV: hidden[bn][w*32 + d] = sum_m v[m] * V[b*512+m][w*32+d]
    // 4-row coalesced groups: lane l -> row mb + (l>>3), float4 (l&7).
    const int rg = l >> 3;
    const float* Vb = vmat + (long)b * 131072 + w * 32 + (l & 7) * 4;
    float4 acc = make_float4(0.f, 0.f, 0.f, 0.f);
#pragma unroll
    for (int j = 0; j < 8; j++) {
        float s0v = v[2 * j], s1v = v[2 * j + 1];
#pragma unroll
        for (int g = 0; g < 16; g++) {
            int r = j * 64 + g * 4 + rg;
            float4 vv = *(const float4*)(Vb + (long)r * 256);
            int src = g * 2 + (rg >> 1);
            float e0 = __shfl_sync(0xFFFFFFFFu, s0v, src);
            float e1 = __shfl_sync(0xFFFFFFFFu, s1v, src);
            float av = (rg & 1) ? e1 : e0;
            acc.x += av * vv.x;
            acc.y += av * vv.y;
            acc.z += av * vv.z;
            acc.w += av * vv.w;
        }
    }
#pragma unroll
    for (int off = 8; off <= 16; off <<= 1) {
        acc.x += __shfl_xor_sync(0xFFFFFFFFu, acc.x, off);
        acc.y += __shfl_xor_sync(0xFFFFFFFFu, acc.y, off);
        acc.z += __shfl_xor_sync(0xFFFFFFFFu, acc.z, off);
        acc.w += __shfl_xor_sync(0xFFFFFFFFu, acc.w, off);
    }
    if (l < 8)
        *(float4*)(hid + bn * 256 + w * 32 + l * 4) = acc;
}

extern "C" void kernel_launch(void* const* d_in, const int* in_sizes, int n_in,
                              void* d_out, int out_size)
{
    const float* iq    = (const float*)d_in[0];
    const float* ik    = (const float*)d_in[1];
    const float* iv    = (const float*)d_in[2];
    const float* embed = (const float*)d_in[3];
    const float* Wq    = (const float*)d_in[4];
    const float* Wk    = (const float*)d_in[5];
    const float* Wv    = (const float*)d_in[6];
    const float* Wp    = (const float*)d_in[7];
    const float* Wout  = (const float*)d_in[8];
    const float* bout  = (const float*)d_in[9];
    float* out = (float*)d_out;

    float *q, *k, *v, *wq, *se, *hid;
    cudaGetSymbolAddress((void**)&q,   g_q);
    cudaGetSymbolAddress((void**)&k,   g_k);
    cudaGetSymbolAddress((void**)&v,   g_v);
    cudaGetSymbolAddress((void**)&wq,  g_wq);
    cudaGetSymbolAddress((void**)&se,  g_se);
    cudaGetSymbolAddress((void**)&hid, g_hid);

    // 1. q/k/v projections (q scaled)
    k_gemm_qkv<<<dim3(16, 4, 3), 256>>>(iq, ik, iv, Wq, Wk, Wv, q, k, v);

    // 2. wq + scores_e (merged)
    k_wq_se<<<dim3(16, 8, 24), 256>>>(q, k, Wp, wq, se);

    // 3. fused scores_p + scores_e + softmax + attn@V -> hidden
    k_fused<<<dim3(512, 2), 256>>>(embed, wq, se, v, hid);

    // 4. out = hidden @ Wout + bout
    k_gemm_out<<<dim3(16, 4, 1), 256>>>(hid, Wout, out, bout);
}